// round 10
// baseline (speedup 1.0000x reference)
#include <cuda_runtime.h>
#include <cstdint>

// WordEmbedding: out[row, :] = W[ids[row], :]
//   W: [50257, 1024] fp32 (4KB rows), ids: [32768] int32, out: [32768,1024] fp32
//
// All execution strategies plateau at ~5.1TB/s -> memory-system ceiling.
// Remaining lever: traffic reduction. The ~24K distinct rows (~96MB) fit L2;
// pin them with evict_last reads, and push the 128MB dead write stream out
// with evict_first stores.

#define DIM 1024
#define VEC_PER_ROW (DIM / 4)   // 256 float4 per row
#define ROWS_PER_CTA 8

__global__ __launch_bounds__(256)
void WordEmbedding_43181601194151_kernel(const float4* __restrict__ w,
                                         const int* __restrict__ ids,
                                         float4* __restrict__ out)
{
    const int base_row = blockIdx.x * ROWS_PER_CTA;
    const int t = threadIdx.x;

    // L2 policies: weight rows sticky, output stream transient.
    unsigned long long pol_keep, pol_drop;
    asm("createpolicy.fractional.L2::evict_last.b64  %0, 1.0;" : "=l"(pol_keep));
    asm("createpolicy.fractional.L2::evict_first.b64 %0, 1.0;" : "=l"(pol_drop));

    const int4* ids4 = (const int4*)(ids + base_row);
    const int4 ia = __ldg(&ids4[0]);
    const int4 ib = __ldg(&ids4[1]);
    const int id[ROWS_PER_CTA] = {ia.x, ia.y, ia.z, ia.w, ib.x, ib.y, ib.z, ib.w};

    // Front-batched gather loads, L2 evict_last (pin working set in L2).
    float4 v[ROWS_PER_CTA];
#pragma unroll
    for (int r = 0; r < ROWS_PER_CTA; r++) {
        const float4* p = w + (((size_t)id[r]) << 8) + t;
        asm volatile("ld.global.nc.L2::cache_hint.v4.f32 {%0,%1,%2,%3}, [%4], %5;"
                     : "=f"(v[r].x), "=f"(v[r].y), "=f"(v[r].z), "=f"(v[r].w)
                     : "l"(p), "l"(pol_keep));
    }

    // Output stores, L2 evict_first (dead data; don't evict weight rows).
#pragma unroll
    for (int r = 0; r < ROWS_PER_CTA; r++) {
        float4* q = out + (((size_t)(base_row + r)) << 8) + t;
        asm volatile("st.global.L2::cache_hint.v4.f32 [%0], {%1,%2,%3,%4}, %5;"
                     :: "l"(q), "f"(v[r].x), "f"(v[r].y), "f"(v[r].z), "f"(v[r].w),
                        "l"(pol_drop)
                     : "memory");
    }
}

extern "C" void kernel_launch(void* const* d_in, const int* in_sizes, int n_in,
                              void* d_out, int out_size)
{
    // Select inputs by size: the weight matrix is by far the larger tensor.
    int w_idx = 0, id_idx = 1;
    if (n_in >= 2 && in_sizes[1] > in_sizes[0]) { w_idx = 1; id_idx = 0; }

    const float4* w   = (const float4*)d_in[w_idx];
    const int*    ids = (const int*)d_in[id_idx];
    float4*       out = (float4*)d_out;

    const int n_rows = out_size / DIM;               // 32768
    const int n_blocks = n_rows / ROWS_PER_CTA;      // 4096

    WordEmbedding_43181601194151_kernel<<<n_blocks, 256>>>(w, ids, out);
}